// round 7
// baseline (speedup 1.0000x reference)
#include <cuda_runtime.h>

#define NMAX 40000
#define EMAX 640000

// Scratch (device globals: allocation-free per harness rules)
__device__ int   g_deg[NMAX];
__device__ int   g_rowptr[NMAX + 1];
__device__ int   g_cursor[NMAX];
__device__ int   g_col[EMAX];
__device__ float g_dinv[NMAX];
__device__ float g_buf0[(size_t)NMAX * 128];
__device__ float g_buf1[(size_t)NMAX * 128];
// Pre-split tf32 fragment-ordered weights: ((kt*BN)+c)*4+qid -> {hi,lo,hi,lo}
__device__ float4 g_pb1[16 * 128 * 4];
__device__ float4 g_pb2[16 * 128 * 4];
__device__ float4 g_pb3[16 * 64 * 4];

// ---------------------------------------------------------------------------
__device__ __forceinline__ float trunc13(float f) {
    return __uint_as_float(__float_as_uint(f) & 0xffffe000u);
}

// ---------------------------------------------------------------------------
// 0) fused prep: zero g_deg + pack all three weight matrices (tf32 hi/lo)
// ---------------------------------------------------------------------------
__device__ __forceinline__ void pack_one(const float* __restrict__ W,
                                         float4* __restrict__ PB, int BN, int j) {
    int qid = j & 3;
    int c   = (j >> 2) % BN;
    int kt  = (j >> 2) / BN;
    float f0 = W[(kt * 8 + qid) * BN + c];
    float f1 = W[(kt * 8 + qid + 4) * BN + c];
    float4 v;
    v.x = trunc13(f0); v.y = f0 - v.x;
    v.z = trunc13(f1); v.w = f1 - v.z;
    PB[j] = v;
}

__global__ void prep_kernel(const float* __restrict__ W1,
                            const float* __restrict__ W2,
                            const float* __restrict__ W3, int N) {
    int i = blockIdx.x * blockDim.x + threadIdx.x;
    if (i < N) { g_deg[i] = 0; return; }
    i -= N;
    if (i < 16 * 128 * 4) { pack_one(W1, g_pb1, 128, i); return; }
    i -= 16 * 128 * 4;
    if (i < 16 * 128 * 4) { pack_one(W2, g_pb2, 128, i); return; }
    i -= 16 * 128 * 4;
    if (i < 16 * 64 * 4)  { pack_one(W3, g_pb3, 64, i); }
}

// ---------------------------------------------------------------------------
// 1) degree count (edges by dst)
// ---------------------------------------------------------------------------
__global__ void deg_kernel(const int* __restrict__ dst, int E, int N) {
    int i = blockIdx.x * blockDim.x + threadIdx.x;
    if (i < E) {
        int d = dst[i];
        d = max(0, min(d, N - 1));
        atomicAdd(&g_deg[d], 1);
    }
}

// ---------------------------------------------------------------------------
// 2) single-kernel exclusive scan (one block, 1024 threads, shfl-based)
//    chunks of 4096 (4/thread); also writes cursor + dinv
// ---------------------------------------------------------------------------
__global__ void __launch_bounds__(1024, 1) scan_all_kernel(int N) {
    __shared__ float carry_s;
    __shared__ float wsum[32];
    int t = threadIdx.x;
    int lane = t & 31, wrp = t >> 5;
    if (t == 0) carry_s = 0;
    __syncthreads();
    for (int base = 0; base < N; base += 4096) {
        int i0 = base + t * 4;
        int v0 = (i0 + 0 < N) ? g_deg[i0 + 0] : 0;
        int v1 = (i0 + 1 < N) ? g_deg[i0 + 1] : 0;
        int v2 = (i0 + 2 < N) ? g_deg[i0 + 2] : 0;
        int v3 = (i0 + 3 < N) ? g_deg[i0 + 3] : 0;
        int s = v0 + v1 + v2 + v3;
        // warp inclusive scan of s
        int sc = s;
        #pragma unroll
        for (int off = 1; off < 32; off <<= 1) {
            int u = __shfl_up_sync(0xffffffffu, sc, off);
            if (lane >= off) sc += u;
        }
        if (lane == 31) wsum[wrp] = (float)sc;  // store warp totals
        __syncthreads();
        if (wrp == 0) {
            int ws = (lane < 32) ? (int)wsum[lane] : 0;
            int wsc = ws;
            #pragma unroll
            for (int off = 1; off < 32; off <<= 1) {
                int u = __shfl_up_sync(0xffffffffu, wsc, off);
                if (lane >= off) wsc += u;
            }
            wsum[lane] = (float)(wsc - ws);   // exclusive warp offsets
        }
        __syncthreads();
        int excl = (int)carry_s + (int)wsum[wrp] + (sc - s);
        // write results
        int run = excl;
        if (i0 + 0 < N) { g_rowptr[i0+0]=run; g_cursor[i0+0]=run; g_dinv[i0+0]=rsqrtf((float)v0+1.f); run+=v0; }
        if (i0 + 1 < N) { g_rowptr[i0+1]=run; g_cursor[i0+1]=run; g_dinv[i0+1]=rsqrtf((float)v1+1.f); run+=v1; }
        if (i0 + 2 < N) { g_rowptr[i0+2]=run; g_cursor[i0+2]=run; g_dinv[i0+2]=rsqrtf((float)v2+1.f); run+=v2; }
        if (i0 + 3 < N) { g_rowptr[i0+3]=run; g_cursor[i0+3]=run; g_dinv[i0+3]=rsqrtf((float)v3+1.f); run+=v3; }
        __syncthreads();
        if (t == 1023) carry_s = (float)(excl + s);
        __syncthreads();
    }
    if (t == 0) g_rowptr[N] = (int)carry_s;
}

// ---------------------------------------------------------------------------
// 3) CSR fill
// ---------------------------------------------------------------------------
__global__ void fill_kernel(const int* __restrict__ src,
                            const int* __restrict__ dst, int E, int N) {
    int i = blockIdx.x * blockDim.x + threadIdx.x;
    if (i < E) {
        int d = max(0, min(dst[i], N - 1));
        int s = max(0, min(src[i], N - 1));
        int pos = atomicAdd(&g_cursor[d], 1);
        g_col[pos] = s;
    }
}

// ---------------------------------------------------------------------------
// 4) Tensor-core GEMM, 3xTF32 (hi*hi + hi*lo + lo*hi), pre-split B fragments
// ---------------------------------------------------------------------------
__device__ __forceinline__ void mma_tf32(float* c, const unsigned* a, const unsigned* b) {
    asm volatile(
        "mma.sync.aligned.m16n8k8.row.col.f32.tf32.tf32.f32 "
        "{%0,%1,%2,%3}, {%4,%5,%6,%7}, {%8,%9}, {%0,%1,%2,%3};\n"
        : "+f"(c[0]), "+f"(c[1]), "+f"(c[2]), "+f"(c[3])
        : "r"(a[0]), "r"(a[1]), "r"(a[2]), "r"(a[3]), "r"(b[0]), "r"(b[1]));
}

template <int BN>
__global__ void __launch_bounds__(256, 1)
mma_gemm_kernel(const float* __restrict__ A,
                const float4* __restrict__ PB,
                float* __restrict__ C, int M) {
    constexpr int NT = BN / 16;
    int tid = threadIdx.x;
    int wid = tid >> 5, lane = tid & 31;
    int warp_m = wid >> 1, warp_n = wid & 1;
    int grp = lane >> 2, qid = lane & 3;
    int m0 = blockIdx.x * 128 + warp_m * 32;
    int col0 = warp_n * (BN / 2);

    float acc[2][NT][4];
    #pragma unroll
    for (int mt = 0; mt < 2; mt++)
        #pragma unroll
        for (int nt = 0; nt < NT; nt++)
            #pragma unroll
            for (int j = 0; j < 4; j++) acc[mt][nt][j] = 0.f;

    #pragma unroll 2
    for (int kt = 0; kt < 16; kt++) {
        int k0 = kt * 8;
        unsigned ahi[2][4], alo[2][4];
        #pragma unroll
        for (int mt = 0; mt < 2; mt++) {
            int r0 = m0 + mt * 16 + grp;
            int r1 = r0 + 8;
            int rc0 = min(r0, M - 1), rc1 = min(r1, M - 1);
            float f0 = A[(size_t)rc0 * 128 + k0 + qid];
            float f1 = A[(size_t)rc1 * 128 + k0 + qid];
            float f2 = A[(size_t)rc0 * 128 + k0 + qid + 4];
            float f3 = A[(size_t)rc1 * 128 + k0 + qid + 4];
            float h0 = trunc13(f0), h1 = trunc13(f1), h2 = trunc13(f2), h3 = trunc13(f3);
            ahi[mt][0] = __float_as_uint(h0); alo[mt][0] = __float_as_uint(f0 - h0);
            ahi[mt][1] = __float_as_uint(h1); alo[mt][1] = __float_as_uint(f1 - h1);
            ahi[mt][2] = __float_as_uint(h2); alo[mt][2] = __float_as_uint(f2 - h2);
            ahi[mt][3] = __float_as_uint(h3); alo[mt][3] = __float_as_uint(f3 - h3);
        }
        #pragma unroll
        for (int nt = 0; nt < NT; nt++) {
            int c = col0 + nt * 8 + grp;
            float4 pb = PB[((kt * BN) + c) * 4 + qid];
            unsigned bh[2] = { __float_as_uint(pb.x), __float_as_uint(pb.z) };
            unsigned bl[2] = { __float_as_uint(pb.y), __float_as_uint(pb.w) };
            #pragma unroll
            for (int mt = 0; mt < 2; mt++) {
                mma_tf32(acc[mt][nt], ahi[mt], bh);
                mma_tf32(acc[mt][nt], ahi[mt], bl);
                mma_tf32(acc[mt][nt], alo[mt], bh);
            }
        }
    }
    #pragma unroll
    for (int mt = 0; mt < 2; mt++) {
        int r0 = m0 + mt * 16 + grp;
        int r1 = r0 + 8;
        #pragma unroll
        for (int nt = 0; nt < NT; nt++) {
            int c = col0 + nt * 8 + qid * 2;
            if (r0 < M) {
                C[(size_t)r0 * BN + c]     = acc[mt][nt][0];
                C[(size_t)r0 * BN + c + 1] = acc[mt][nt][1];
            }
            if (r1 < M) {
                C[(size_t)r1 * BN + c]     = acc[mt][nt][2];
                C[(size_t)r1 * BN + c + 1] = acc[mt][nt][3];
            }
        }
    }
}

// ---------------------------------------------------------------------------
// 5) Aggregation D=128: warp per node, CSR gather (unroll 8), +self,+bias,ReLU
// ---------------------------------------------------------------------------
template <bool RELU>
__global__ void agg128_kernel(const float* __restrict__ hin,
                              float* __restrict__ hout,
                              const float* __restrict__ bias, int N) {
    int warp = (blockIdx.x * blockDim.x + threadIdx.x) >> 5;
    int lane = threadIdx.x & 31;
    if (warp >= N) return;

    float dn = g_dinv[warp];
    float acc[4];
    {
        float ws = dn * dn;
        float4 v = *(const float4*)(hin + (size_t)warp * 128 + lane * 4);
        acc[0] = ws * v.x; acc[1] = ws * v.y; acc[2] = ws * v.z; acc[3] = ws * v.w;
    }
    int e = g_rowptr[warp];
    const int e1 = g_rowptr[warp + 1];
    for (; e + 8 <= e1; e += 8) {
        int sA[8];
        #pragma unroll
        for (int j = 0; j < 8; j++) sA[j] = g_col[e + j];
        float w[8];
        #pragma unroll
        for (int j = 0; j < 8; j++) w[j] = g_dinv[sA[j]] * dn;
        float4 v[8];
        #pragma unroll
        for (int j = 0; j < 8; j++)
            v[j] = *(const float4*)(hin + (size_t)sA[j] * 128 + lane * 4);
        #pragma unroll
        for (int j = 0; j < 8; j++) {
            acc[0] += w[j] * v[j].x; acc[1] += w[j] * v[j].y;
            acc[2] += w[j] * v[j].z; acc[3] += w[j] * v[j].w;
        }
    }
    for (; e < e1; e++) {
        int s = g_col[e];
        float w = g_dinv[s] * dn;
        float4 v = *(const float4*)(hin + (size_t)s * 128 + lane * 4);
        acc[0] += w * v.x; acc[1] += w * v.y; acc[2] += w * v.z; acc[3] += w * v.w;
    }
    float4 b = *(const float4*)(bias + lane * 4);
    float4 o = make_float4(acc[0] + b.x, acc[1] + b.y, acc[2] + b.z, acc[3] + b.w);
    if (RELU) {
        o.x = fmaxf(o.x, 0.f); o.y = fmaxf(o.y, 0.f);
        o.z = fmaxf(o.z, 0.f); o.w = fmaxf(o.w, 0.f);
    }
    *(float4*)(hout + (size_t)warp * 128 + lane * 4) = o;
}

// ---------------------------------------------------------------------------
// 5b) Aggregation D=64 with fused output head (unroll 8)
// ---------------------------------------------------------------------------
__global__ void agg64_out_kernel(const float* __restrict__ hin,
                                 float* __restrict__ hout,
                                 const float* __restrict__ bias,
                                 const float* __restrict__ Wout,
                                 const float* __restrict__ bout,
                                 float* __restrict__ out, int N) {
    int warp = (blockIdx.x * blockDim.x + threadIdx.x) >> 5;
    int lane = threadIdx.x & 31;
    if (warp >= N) return;

    float dn = g_dinv[warp];
    float a0, a1;
    {
        float ws = dn * dn;
        float2 v = *(const float2*)(hin + (size_t)warp * 64 + lane * 2);
        a0 = ws * v.x; a1 = ws * v.y;
    }
    int e = g_rowptr[warp];
    const int e1 = g_rowptr[warp + 1];
    for (; e + 8 <= e1; e += 8) {
        int sA[8];
        #pragma unroll
        for (int j = 0; j < 8; j++) sA[j] = g_col[e + j];
        float w[8];
        #pragma unroll
        for (int j = 0; j < 8; j++) w[j] = g_dinv[sA[j]] * dn;
        float2 v[8];
        #pragma unroll
        for (int j = 0; j < 8; j++)
            v[j] = *(const float2*)(hin + (size_t)sA[j] * 64 + lane * 2);
        #pragma unroll
        for (int j = 0; j < 8; j++) { a0 += w[j] * v[j].x; a1 += w[j] * v[j].y; }
    }
    for (; e < e1; e++) {
        int s = g_col[e];
        float w = g_dinv[s] * dn;
        float2 v = *(const float2*)(hin + (size_t)s * 64 + lane * 2);
        a0 += w * v.x; a1 += w * v.y;
    }
    float2 b = *(const float2*)(bias + lane * 2);
    float2 o = make_float2(a0 + b.x, a1 + b.y);
    *(float2*)(hout + (size_t)warp * 64 + lane * 2) = o;

    // fused head: out[warp][j] = sum_c h[c]*Wout[c][j] + bout[j]
    int c0 = lane * 2;
    float p0 = o.x * __ldg(&Wout[c0 * 2])     + o.y * __ldg(&Wout[(c0 + 1) * 2]);
    float p1 = o.x * __ldg(&Wout[c0 * 2 + 1]) + o.y * __ldg(&Wout[(c0 + 1) * 2 + 1]);
    #pragma unroll
    for (int off = 16; off > 0; off >>= 1) {
        p0 += __shfl_xor_sync(0xffffffffu, p0, off);
        p1 += __shfl_xor_sync(0xffffffffu, p1, off);
    }
    if (lane == 0) {
        out[(size_t)warp * 2 + 0] = p0 + __ldg(&bout[0]);
        out[(size_t)warp * 2 + 1] = p1 + __ldg(&bout[1]);
    }
}

// ---------------------------------------------------------------------------
extern "C" void kernel_launch(void* const* d_in, const int* in_sizes, int n_in,
                              void* d_out, int out_size) {
    (void)n_in; (void)out_size;
    const float* x    = (const float*)d_in[0];
    const int*   ei   = (const int*)d_in[1];   // int32 (JAX default x64 off)
    const float* W1   = (const float*)d_in[2];
    const float* b1   = (const float*)d_in[3];
    const float* W2   = (const float*)d_in[4];
    const float* b2   = (const float*)d_in[5];
    const float* W3   = (const float*)d_in[6];
    const float* b3   = (const float*)d_in[7];
    const float* Wout = (const float*)d_in[8];
    const float* bout = (const float*)d_in[9];

    int N = in_sizes[0] / 128;
    int E = in_sizes[1] / 2;

    float* out  = (float*)d_out;
    float* hout = out + (size_t)N * 2;   // tuple layout: out[N,2] then h[N,64]

    float* buf0; cudaGetSymbolAddress((void**)&buf0, g_buf0);
    float* buf1; cudaGetSymbolAddress((void**)&buf1, g_buf1);
    float4* pb1; cudaGetSymbolAddress((void**)&pb1, g_pb1);
    float4* pb2; cudaGetSymbolAddress((void**)&pb2, g_pb2);
    float4* pb3; cudaGetSymbolAddress((void**)&pb3, g_pb3);

    const int* src = ei;
    const int* dst = ei + E;

    // fused prep: zero deg + pack three weight matrices
    int prep_total = N + 16 * 128 * 4 + 16 * 128 * 4 + 16 * 64 * 4;
    prep_kernel<<<(prep_total + 255) / 256, 256>>>(W1, W2, W3, N);

    // CSR build
    deg_kernel<<<(E + 255) / 256, 256>>>(dst, E, N);
    scan_all_kernel<<<1, 1024>>>(N);
    fill_kernel<<<(E + 255) / 256, 256>>>(src, dst, E, N);

    int gM = (N + 127) / 128;
    int gW = (N * 32 + 255) / 256;

    // Layer 1
    mma_gemm_kernel<128><<<gM, 256>>>(x, pb1, buf0, N);
    agg128_kernel<true><<<gW, 256>>>(buf0, buf1, b1, N);
    // Layer 2
    mma_gemm_kernel<128><<<gM, 256>>>(buf1, pb2, buf0, N);
    agg128_kernel<true><<<gW, 256>>>(buf0, buf1, b2, N);
    // Layer 3 + fused output head
    mma_gemm_kernel<64><<<gM, 256>>>(buf1, pb3, buf0, N);
    agg64_out_kernel<<<gW, 256>>>(buf0, hout, b3, Wout, bout, out, N);
}

// round 8
// speedup vs baseline: 1.1374x; 1.1374x over previous
#include <cuda_runtime.h>

#define NMAX 40000
#define EMAX 640000

// Scratch (device globals: allocation-free per harness rules)
__device__ int   g_deg[NMAX];
__device__ int   g_rowptr[NMAX + 1];
__device__ int   g_cursor[NMAX];
__device__ int   g_col[EMAX];
__device__ float g_dinv[NMAX];
__device__ int   g_bsum[64];
__device__ float g_buf0[(size_t)NMAX * 128];
__device__ float g_buf1[(size_t)NMAX * 128];
// Pre-split fragment-ordered weights: [kt][c][qid] -> {hi(k0+qid,c), lo, hi(k0+qid+4,c), lo}
__device__ float4 g_pb1[16 * 128 * 4];
__device__ float4 g_pb2[16 * 128 * 4];
__device__ float4 g_pb3[16 * 64 * 4];

// ---------------------------------------------------------------------------
__device__ __forceinline__ float trunc13(float f) {
    return __uint_as_float(__float_as_uint(f) & 0xffffe000u);
}

// ---------------------------------------------------------------------------
// 0) zero degree array
// ---------------------------------------------------------------------------
__global__ void zero_deg_kernel(int N) {
    int i = blockIdx.x * blockDim.x + threadIdx.x;
    if (i < N) g_deg[i] = 0;
}

// ---------------------------------------------------------------------------
// 1) degree count (edges by dst), 4 edges per thread via int4
// ---------------------------------------------------------------------------
__global__ void deg_kernel(const int* __restrict__ dst, int E, int N) {
    int i = blockIdx.x * blockDim.x + threadIdx.x;
    int e0 = i * 4;
    if (e0 + 4 <= E) {
        int4 d4 = *(const int4*)(dst + e0);
        atomicAdd(&g_deg[max(0, min(d4.x, N - 1))], 1);
        atomicAdd(&g_deg[max(0, min(d4.y, N - 1))], 1);
        atomicAdd(&g_deg[max(0, min(d4.z, N - 1))], 1);
        atomicAdd(&g_deg[max(0, min(d4.w, N - 1))], 1);
    } else {
        for (int e = e0; e < E; e++)
            atomicAdd(&g_deg[max(0, min(dst[e], N - 1))], 1);
    }
}

// ---------------------------------------------------------------------------
// 2) hierarchical exclusive scan -> rowptr/cursor + dinv
// ---------------------------------------------------------------------------
__global__ void scan1_kernel(int N) {
    __shared__ int sh[256];
    int t = threadIdx.x;
    int base = blockIdx.x * 1024 + t * 4;
    int s = 0;
    #pragma unroll
    for (int i = 0; i < 4; i++) if (base + i < N) s += g_deg[base + i];
    sh[t] = s;
    __syncthreads();
    #pragma unroll
    for (int off = 128; off > 0; off >>= 1) {
        if (t < off) sh[t] += sh[t + off];
        __syncthreads();
    }
    if (t == 0) g_bsum[blockIdx.x] = sh[0];
}

__global__ void scan2_kernel(int nb, int N) {
    if (threadIdx.x == 0) {
        int run = 0;
        for (int i = 0; i < nb; i++) { int v = g_bsum[i]; g_bsum[i] = run; run += v; }
        g_rowptr[N] = run;
    }
}

__global__ void scan3_kernel(int N) {
    __shared__ int sh[256];
    int t = threadIdx.x;
    int base = blockIdx.x * 1024 + t * 4;
    int v[4];
    int s = 0;
    #pragma unroll
    for (int i = 0; i < 4; i++) {
        v[i] = (base + i < N) ? g_deg[base + i] : 0;
        s += v[i];
    }
    sh[t] = s;
    __syncthreads();
    #pragma unroll
    for (int off = 1; off < 256; off <<= 1) {
        int x = (t >= off) ? sh[t - off] : 0;
        __syncthreads();
        sh[t] += x;
        __syncthreads();
    }
    int run = g_bsum[blockIdx.x] + sh[t] - s;
    #pragma unroll
    for (int i = 0; i < 4; i++) {
        int idx = base + i;
        if (idx < N) {
            g_rowptr[idx] = run;
            g_cursor[idx] = run;
            g_dinv[idx]   = rsqrtf((float)v[i] + 1.0f);
            run += v[i];
        }
    }
}

// ---------------------------------------------------------------------------
// 3) CSR fill, 4 edges per thread via int4 (MLP=4 on the atomic chain)
// ---------------------------------------------------------------------------
__global__ void fill_kernel(const int* __restrict__ src,
                            const int* __restrict__ dst, int E, int N) {
    int i = blockIdx.x * blockDim.x + threadIdx.x;
    int e0 = i * 4;
    if (e0 + 4 <= E) {
        int4 d4 = *(const int4*)(dst + e0);
        int4 s4 = *(const int4*)(src + e0);
        int p0 = atomicAdd(&g_cursor[max(0, min(d4.x, N - 1))], 1);
        int p1 = atomicAdd(&g_cursor[max(0, min(d4.y, N - 1))], 1);
        int p2 = atomicAdd(&g_cursor[max(0, min(d4.z, N - 1))], 1);
        int p3 = atomicAdd(&g_cursor[max(0, min(d4.w, N - 1))], 1);
        g_col[p0] = max(0, min(s4.x, N - 1));
        g_col[p1] = max(0, min(s4.y, N - 1));
        g_col[p2] = max(0, min(s4.z, N - 1));
        g_col[p3] = max(0, min(s4.w, N - 1));
    } else {
        for (int e = e0; e < E; e++) {
            int pos = atomicAdd(&g_cursor[max(0, min(dst[e], N - 1))], 1);
            g_col[pos] = max(0, min(src[e], N - 1));
        }
    }
}

// ---------------------------------------------------------------------------
// 3b) pack weights into fragment-ordered split form (once per launch, cheap)
// ---------------------------------------------------------------------------
__global__ void pack_w_kernel(const float* __restrict__ W, float4* __restrict__ PB, int BN) {
    int i = blockIdx.x * blockDim.x + threadIdx.x;
    int total = 16 * BN * 4;
    if (i >= total) return;
    int qid = i & 3;
    int c   = (i >> 2) % BN;
    int kt  = (i >> 2) / BN;
    float f0 = W[(kt * 8 + qid) * BN + c];
    float f1 = W[(kt * 8 + qid + 4) * BN + c];
    float4 v;
    v.x = trunc13(f0); v.y = f0 - v.x;
    v.z = trunc13(f1); v.w = f1 - v.z;
    PB[i] = v;
}

// ---------------------------------------------------------------------------
// 4) Tensor-core GEMM, 3xTF32 (hi*hi + hi*lo + lo*hi), pre-split B fragments
// ---------------------------------------------------------------------------
__device__ __forceinline__ void mma_tf32(float* c, const unsigned* a, const unsigned* b) {
    asm volatile(
        "mma.sync.aligned.m16n8k8.row.col.f32.tf32.tf32.f32 "
        "{%0,%1,%2,%3}, {%4,%5,%6,%7}, {%8,%9}, {%0,%1,%2,%3};\n"
        : "+f"(c[0]), "+f"(c[1]), "+f"(c[2]), "+f"(c[3])
        : "r"(a[0]), "r"(a[1]), "r"(a[2]), "r"(a[3]), "r"(b[0]), "r"(b[1]));
}

template <int BN>
__global__ void __launch_bounds__(256, 1)
mma_gemm_kernel(const float* __restrict__ A,
                const float4* __restrict__ PB,
                float* __restrict__ C, int M) {
    constexpr int NT = BN / 16;
    int tid = threadIdx.x;
    int wid = tid >> 5, lane = tid & 31;
    int warp_m = wid >> 1, warp_n = wid & 1;
    int grp = lane >> 2, qid = lane & 3;
    int m0 = blockIdx.x * 128 + warp_m * 32;
    int col0 = warp_n * (BN / 2);

    float acc[2][NT][4];
    #pragma unroll
    for (int mt = 0; mt < 2; mt++)
        #pragma unroll
        for (int nt = 0; nt < NT; nt++)
            #pragma unroll
            for (int j = 0; j < 4; j++) acc[mt][nt][j] = 0.f;

    #pragma unroll 2
    for (int kt = 0; kt < 16; kt++) {
        int k0 = kt * 8;
        unsigned ahi[2][4], alo[2][4];
        #pragma unroll
        for (int mt = 0; mt < 2; mt++) {
            int r0 = m0 + mt * 16 + grp;
            int r1 = r0 + 8;
            int rc0 = min(r0, M - 1), rc1 = min(r1, M - 1);
            float f0 = A[(size_t)rc0 * 128 + k0 + qid];
            float f1 = A[(size_t)rc1 * 128 + k0 + qid];
            float f2 = A[(size_t)rc0 * 128 + k0 + qid + 4];
            float f3 = A[(size_t)rc1 * 128 + k0 + qid + 4];
            float h0 = trunc13(f0), h1 = trunc13(f1), h2 = trunc13(f2), h3 = trunc13(f3);
            ahi[mt][0] = __float_as_uint(h0); alo[mt][0] = __float_as_uint(f0 - h0);
            ahi[mt][1] = __float_as_uint(h1); alo[mt][1] = __float_as_uint(f1 - h1);
            ahi[mt][2] = __float_as_uint(h2); alo[mt][2] = __float_as_uint(f2 - h2);
            ahi[mt][3] = __float_as_uint(h3); alo[mt][3] = __float_as_uint(f3 - h3);
        }
        #pragma unroll
        for (int nt = 0; nt < NT; nt++) {
            int c = col0 + nt * 8 + grp;
            float4 pb = PB[((kt * BN) + c) * 4 + qid];
            unsigned bh[2] = { __float_as_uint(pb.x), __float_as_uint(pb.z) };
            unsigned bl[2] = { __float_as_uint(pb.y), __float_as_uint(pb.w) };
            #pragma unroll
            for (int mt = 0; mt < 2; mt++) {
                mma_tf32(acc[mt][nt], ahi[mt], bh);
                mma_tf32(acc[mt][nt], ahi[mt], bl);
                mma_tf32(acc[mt][nt], alo[mt], bh);
            }
        }
    }
    #pragma unroll
    for (int mt = 0; mt < 2; mt++) {
        int r0 = m0 + mt * 16 + grp;
        int r1 = r0 + 8;
        #pragma unroll
        for (int nt = 0; nt < NT; nt++) {
            int c = col0 + nt * 8 + qid * 2;
            if (r0 < M) {
                C[(size_t)r0 * BN + c]     = acc[mt][nt][0];
                C[(size_t)r0 * BN + c + 1] = acc[mt][nt][1];
            }
            if (r1 < M) {
                C[(size_t)r1 * BN + c]     = acc[mt][nt][2];
                C[(size_t)r1 * BN + c + 1] = acc[mt][nt][3];
            }
        }
    }
}

// ---------------------------------------------------------------------------
// 5) Aggregation D=128: warp per node, CSR gather (unroll 4), +self,+bias,ReLU
// ---------------------------------------------------------------------------
template <bool RELU>
__global__ void agg128_kernel(const float* __restrict__ hin,
                              float* __restrict__ hout,
                              const float* __restrict__ bias, int N) {
    int warp = (blockIdx.x * blockDim.x + threadIdx.x) >> 5;
    int lane = threadIdx.x & 31;
    if (warp >= N) return;

    float dn = g_dinv[warp];
    float acc[4];
    {
        float ws = dn * dn;
        float4 v = *(const float4*)(hin + (size_t)warp * 128 + lane * 4);
        acc[0] = ws * v.x; acc[1] = ws * v.y; acc[2] = ws * v.z; acc[3] = ws * v.w;
    }
    int e = g_rowptr[warp];
    const int e1 = g_rowptr[warp + 1];
    for (; e + 4 <= e1; e += 4) {
        int s0 = g_col[e], s1 = g_col[e + 1], s2 = g_col[e + 2], s3 = g_col[e + 3];
        float w0 = g_dinv[s0] * dn, w1 = g_dinv[s1] * dn;
        float w2 = g_dinv[s2] * dn, w3 = g_dinv[s3] * dn;
        float4 v0 = *(const float4*)(hin + (size_t)s0 * 128 + lane * 4);
        float4 v1 = *(const float4*)(hin + (size_t)s1 * 128 + lane * 4);
        float4 v2 = *(const float4*)(hin + (size_t)s2 * 128 + lane * 4);
        float4 v3 = *(const float4*)(hin + (size_t)s3 * 128 + lane * 4);
        acc[0] += w0 * v0.x + w1 * v1.x + w2 * v2.x + w3 * v3.x;
        acc[1] += w0 * v0.y + w1 * v1.y + w2 * v2.y + w3 * v3.y;
        acc[2] += w0 * v0.z + w1 * v1.z + w2 * v2.z + w3 * v3.z;
        acc[3] += w0 * v0.w + w1 * v1.w + w2 * v2.w + w3 * v3.w;
    }
    for (; e < e1; e++) {
        int s = g_col[e];
        float w = g_dinv[s] * dn;
        float4 v = *(const float4*)(hin + (size_t)s * 128 + lane * 4);
        acc[0] += w * v.x; acc[1] += w * v.y; acc[2] += w * v.z; acc[3] += w * v.w;
    }
    float4 b = *(const float4*)(bias + lane * 4);
    float4 o = make_float4(acc[0] + b.x, acc[1] + b.y, acc[2] + b.z, acc[3] + b.w);
    if (RELU) {
        o.x = fmaxf(o.x, 0.f); o.y = fmaxf(o.y, 0.f);
        o.z = fmaxf(o.z, 0.f); o.w = fmaxf(o.w, 0.f);
    }
    *(float4*)(hout + (size_t)warp * 128 + lane * 4) = o;
}

// ---------------------------------------------------------------------------
// 5b) Aggregation D=64 with fused output head (unroll 4)
// ---------------------------------------------------------------------------
__global__ void agg64_out_kernel(const float* __restrict__ hin,
                                 float* __restrict__ hout,
                                 const float* __restrict__ bias,
                                 const float* __restrict__ Wout,
                                 const float* __restrict__ bout,
                                 float* __restrict__ out, int N) {
    int warp = (blockIdx.x * blockDim.x + threadIdx.x) >> 5;
    int lane = threadIdx.x & 31;
    if (warp >= N) return;

    float dn = g_dinv[warp];
    float a0, a1;
    {
        float ws = dn * dn;
        float2 v = *(const float2*)(hin + (size_t)warp * 64 + lane * 2);
        a0 = ws * v.x; a1 = ws * v.y;
    }
    int e = g_rowptr[warp];
    const int e1 = g_rowptr[warp + 1];
    for (; e + 4 <= e1; e += 4) {
        int s0 = g_col[e], s1 = g_col[e + 1], s2 = g_col[e + 2], s3 = g_col[e + 3];
        float w0 = g_dinv[s0] * dn, w1 = g_dinv[s1] * dn;
        float w2 = g_dinv[s2] * dn, w3 = g_dinv[s3] * dn;
        float2 v0 = *(const float2*)(hin + (size_t)s0 * 64 + lane * 2);
        float2 v1 = *(const float2*)(hin + (size_t)s1 * 64 + lane * 2);
        float2 v2 = *(const float2*)(hin + (size_t)s2 * 64 + lane * 2);
        float2 v3 = *(const float2*)(hin + (size_t)s3 * 64 + lane * 2);
        a0 += w0 * v0.x + w1 * v1.x + w2 * v2.x + w3 * v3.x;
        a1 += w0 * v0.y + w1 * v1.y + w2 * v2.y + w3 * v3.y;
    }
    for (; e < e1; e++) {
        int s = g_col[e];
        float w = g_dinv[s] * dn;
        float2 v = *(const float2*)(hin + (size_t)s * 64 + lane * 2);
        a0 += w * v.x; a1 += w * v.y;
    }
    float2 b = *(const float2*)(bias + lane * 2);
    float2 o = make_float2(a0 + b.x, a1 + b.y);
    *(float2*)(hout + (size_t)warp * 64 + lane * 2) = o;

    // fused head: out[warp][j] = sum_c h[c]*Wout[c][j] + bout[j]
    int c0 = lane * 2;
    float p0 = o.x * __ldg(&Wout[c0 * 2])     + o.y * __ldg(&Wout[(c0 + 1) * 2]);
    float p1 = o.x * __ldg(&Wout[c0 * 2 + 1]) + o.y * __ldg(&Wout[(c0 + 1) * 2 + 1]);
    #pragma unroll
    for (int off = 16; off > 0; off >>= 1) {
        p0 += __shfl_xor_sync(0xffffffffu, p0, off);
        p1 += __shfl_xor_sync(0xffffffffu, p1, off);
    }
    if (lane == 0) {
        out[(size_t)warp * 2 + 0] = p0 + __ldg(&bout[0]);
        out[(size_t)warp * 2 + 1] = p1 + __ldg(&bout[1]);
    }
}

// ---------------------------------------------------------------------------
extern "C" void kernel_launch(void* const* d_in, const int* in_sizes, int n_in,
                              void* d_out, int out_size) {
    (void)n_in; (void)out_size;
    const float* x    = (const float*)d_in[0];
    const int*   ei   = (const int*)d_in[1];   // int32 (JAX default x64 off)
    const float* W1   = (const float*)d_in[2];
    const float* b1   = (const float*)d_in[3];
    const float* W2   = (const float*)d_in[4];
    const float* b2   = (const float*)d_in[5];
    const float* W3   = (const float*)d_in[6];
    const float* b3   = (const float*)d_in[7];
    const float* Wout = (const float*)d_in[8];
    const float* bout = (const float*)d_in[9];

    int N = in_sizes[0] / 128;
    int E = in_sizes[1] / 2;

    float* out  = (float*)d_out;
    float* hout = out + (size_t)N * 2;   // tuple layout: out[N,2] then h[N,64]

    float* buf0; cudaGetSymbolAddress((void**)&buf0, g_buf0);
    float* buf1; cudaGetSymbolAddress((void**)&buf1, g_buf1);
    float4* pb1; cudaGetSymbolAddress((void**)&pb1, g_pb1);
    float4* pb2; cudaGetSymbolAddress((void**)&pb2, g_pb2);
    float4* pb3; cudaGetSymbolAddress((void**)&pb3, g_pb3);

    const int* src = ei;
    const int* dst = ei + E;

    // weight pre-split (fragment order)
    pack_w_kernel<<<(16 * 128 * 4 + 255) / 256, 256>>>(W1, pb1, 128);
    pack_w_kernel<<<(16 * 128 * 4 + 255) / 256, 256>>>(W2, pb2, 128);
    pack_w_kernel<<<(16 * 64 * 4 + 255) / 256, 256>>>(W3, pb3, 64);

    // CSR build
    int nb = (N + 1023) / 1024;
    int e4 = (E + 3) / 4;
    zero_deg_kernel<<<(N + 255) / 256, 256>>>(N);
    deg_kernel<<<(e4 + 255) / 256, 256>>>(dst, E, N);
    scan1_kernel<<<nb, 256>>>(N);
    scan2_kernel<<<1, 32>>>(nb, N);
    scan3_kernel<<<nb, 256>>>(N);
    fill_kernel<<<(e4 + 255) / 256, 256>>>(src, dst, E, N);

    int gM = (N + 127) / 128;
    int gW = (N * 32 + 255) / 256;

    // Layer 1
    mma_gemm_kernel<128><<<gM, 256>>>(x, pb1, buf0, N);
    agg128_kernel<true><<<gW, 256>>>(buf0, buf1, b1, N);
    // Layer 2
    mma_gemm_kernel<128><<<gM, 256>>>(buf1, pb2, buf0, N);
    agg128_kernel<true><<<gW, 256>>>(buf0, buf1, b2, N);
    // Layer 3 + fused output head
    mma_gemm_kernel<64><<<gM, 256>>>(buf1, pb3, buf0, N);
    agg64_out_kernel<<<gW, 256>>>(buf0, hout, b3, Wout, bout, out, N);
}

// round 11
// speedup vs baseline: 1.1711x; 1.0297x over previous
#include <cuda_runtime.h>
#include <cstdint>

#define NMAX 40000
#define EMAX 640000

// Scratch (device globals: allocation-free per harness rules)
__device__ int   g_deg[NMAX];
__device__ int   g_rowptr[NMAX + 1];
__device__ int   g_cursor[NMAX];
__device__ int   g_col[EMAX];
__device__ float g_dinv[NMAX];
__device__ int   g_bsum[64];
__device__ float g_buf0[(size_t)NMAX * 128];
__device__ float g_buf1[(size_t)NMAX * 128];
// Pre-split tf32 fragment-ordered weights: ((kt*BN)+c)*4+qid -> {hi,lo,hi,lo}
__device__ float4 g_pb1[16 * 128 * 4];
__device__ float4 g_pb2[16 * 128 * 4];
__device__ float4 g_pb3[16 * 64 * 4];

// ---------------------------------------------------------------------------
__device__ __forceinline__ float trunc13(float f) {
    return __uint_as_float(__float_as_uint(f) & 0xffffe000u);
}

// ---------------------------------------------------------------------------
// 0) zero degree array
// ---------------------------------------------------------------------------
__global__ void zero_deg_kernel(int N) {
    int i = blockIdx.x * blockDim.x + threadIdx.x;
    if (i < N) g_deg[i] = 0;
}

// ---------------------------------------------------------------------------
// 1) degree count (edges by dst), 4 edges per thread via int4
// ---------------------------------------------------------------------------
__global__ void deg_kernel(const int* __restrict__ dst, int E, int N) {
    int i = blockIdx.x * blockDim.x + threadIdx.x;
    int e0 = i * 4;
    if (e0 + 4 <= E) {
        int4 d4 = *(const int4*)(dst + e0);
        atomicAdd(&g_deg[max(0, min(d4.x, N - 1))], 1);
        atomicAdd(&g_deg[max(0, min(d4.y, N - 1))], 1);
        atomicAdd(&g_deg[max(0, min(d4.z, N - 1))], 1);
        atomicAdd(&g_deg[max(0, min(d4.w, N - 1))], 1);
    } else {
        for (int e = e0; e < E; e++)
            atomicAdd(&g_deg[max(0, min(dst[e], N - 1))], 1);
    }
}

// ---------------------------------------------------------------------------
// 2) hierarchical exclusive scan -> rowptr/cursor + dinv
// ---------------------------------------------------------------------------
__global__ void scan1_kernel(int N) {
    __shared__ int sh[256];
    int t = threadIdx.x;
    int base = blockIdx.x * 1024 + t * 4;
    int s = 0;
    #pragma unroll
    for (int i = 0; i < 4; i++) if (base + i < N) s += g_deg[base + i];
    sh[t] = s;
    __syncthreads();
    #pragma unroll
    for (int off = 128; off > 0; off >>= 1) {
        if (t < off) sh[t] += sh[t + off];
        __syncthreads();
    }
    if (t == 0) g_bsum[blockIdx.x] = sh[0];
}

__global__ void scan2_kernel(int nb, int N) {
    if (threadIdx.x == 0) {
        int run = 0;
        for (int i = 0; i < nb; i++) { int v = g_bsum[i]; g_bsum[i] = run; run += v; }
        g_rowptr[N] = run;
    }
}

__global__ void scan3_kernel(int N) {
    __shared__ int sh[256];
    int t = threadIdx.x;
    int base = blockIdx.x * 1024 + t * 4;
    int v[4];
    int s = 0;
    #pragma unroll
    for (int i = 0; i < 4; i++) {
        v[i] = (base + i < N) ? g_deg[base + i] : 0;
        s += v[i];
    }
    sh[t] = s;
    __syncthreads();
    #pragma unroll
    for (int off = 1; off < 256; off <<= 1) {
        int x = (t >= off) ? sh[t - off] : 0;
        __syncthreads();
        sh[t] += x;
        __syncthreads();
    }
    int run = g_bsum[blockIdx.x] + sh[t] - s;
    #pragma unroll
    for (int i = 0; i < 4; i++) {
        int idx = base + i;
        if (idx < N) {
            g_rowptr[idx] = run;
            g_cursor[idx] = run;
            g_dinv[idx]   = rsqrtf((float)v[i] + 1.0f);
            run += v[i];
        }
    }
}

// ---------------------------------------------------------------------------
// 3) CSR fill, 4 edges per thread via int4
// ---------------------------------------------------------------------------
__global__ void fill_kernel(const int* __restrict__ src,
                            const int* __restrict__ dst, int E, int N) {
    int i = blockIdx.x * blockDim.x + threadIdx.x;
    int e0 = i * 4;
    if (e0 + 4 <= E) {
        int4 d4 = *(const int4*)(dst + e0);
        int4 s4 = *(const int4*)(src + e0);
        int p0 = atomicAdd(&g_cursor[max(0, min(d4.x, N - 1))], 1);
        int p1 = atomicAdd(&g_cursor[max(0, min(d4.y, N - 1))], 1);
        int p2 = atomicAdd(&g_cursor[max(0, min(d4.z, N - 1))], 1);
        int p3 = atomicAdd(&g_cursor[max(0, min(d4.w, N - 1))], 1);
        g_col[p0] = max(0, min(s4.x, N - 1));
        g_col[p1] = max(0, min(s4.y, N - 1));
        g_col[p2] = max(0, min(s4.z, N - 1));
        g_col[p3] = max(0, min(s4.w, N - 1));
    } else {
        for (int e = e0; e < E; e++) {
            int pos = atomicAdd(&g_cursor[max(0, min(dst[e], N - 1))], 1);
            g_col[pos] = max(0, min(src[e], N - 1));
        }
    }
}

// ---------------------------------------------------------------------------
// 3b) pack weights into fragment-ordered split form (once per launch, cheap)
// ---------------------------------------------------------------------------
__global__ void pack_w_kernel(const float* __restrict__ W, float4* __restrict__ PB, int BN) {
    int i = blockIdx.x * blockDim.x + threadIdx.x;
    int total = 16 * BN * 4;
    if (i >= total) return;
    int qid = i & 3;
    int c   = (i >> 2) % BN;
    int kt  = (i >> 2) / BN;
    float f0 = W[(kt * 8 + qid) * BN + c];
    float f1 = W[(kt * 8 + qid + 4) * BN + c];
    float4 v;
    v.x = trunc13(f0); v.y = f0 - v.x;
    v.z = trunc13(f1); v.w = f1 - v.z;
    PB[i] = v;
}

// ---------------------------------------------------------------------------
// 4) Tensor-core GEMM, 3xTF32, A staged through shared memory (conflict-free),
//    pre-split B fragments from global (L2-resident)
// ---------------------------------------------------------------------------
__device__ __forceinline__ void mma_tf32(float* c, const unsigned* a, const unsigned* b) {
    asm volatile(
        "mma.sync.aligned.m16n8k8.row.col.f32.tf32.tf32.f32 "
        "{%0,%1,%2,%3}, {%4,%5,%6,%7}, {%8,%9}, {%0,%1,%2,%3};\n"
        : "+f"(c[0]), "+f"(c[1]), "+f"(c[2]), "+f"(c[3])
        : "r"(a[0]), "r"(a[1]), "r"(a[2]), "r"(a[3]), "r"(b[0]), "r"(b[1]));
}

#define A_STRIDE 132   // floats per row (128 + 4 pad -> bank = (4r+k)&31, conflict-free)
#define A_SMEM_BYTES (128 * A_STRIDE * 4)

template <int BN>
__global__ void __launch_bounds__(256, 1)
mma_gemm_kernel(const float* __restrict__ A,
                const float4* __restrict__ PB,
                float* __restrict__ C, int M) {
    constexpr int NT = BN / 16;
    extern __shared__ float As[];   // [128][A_STRIDE]
    int tid = threadIdx.x;
    int wid = tid >> 5, lane = tid & 31;
    int warp_m = wid >> 1, warp_n = wid & 1;
    int grp = lane >> 2, qid = lane & 3;
    int m0 = blockIdx.x * 128;
    int col0 = warp_n * (BN / 2);

    // ---- stage A tile: coalesced float4 loads, one row per warp-iteration ----
    for (int idx = tid; idx < 128 * 32; idx += 256) {
        int r = idx >> 5;
        int c4 = (idx & 31) * 4;
        int gr = min(m0 + r, M - 1);
        float4 v = *(const float4*)(A + (size_t)gr * 128 + c4);
        *(float4*)(As + r * A_STRIDE + c4) = v;
    }
    __syncthreads();

    float acc[2][NT][4];
    #pragma unroll
    for (int mt = 0; mt < 2; mt++)
        #pragma unroll
        for (int nt = 0; nt < NT; nt++)
            #pragma unroll
            for (int j = 0; j < 4; j++) acc[mt][nt][j] = 0.f;

    int ar0 = warp_m * 32 + grp;       // local row for mt=0
    #pragma unroll 2
    for (int kt = 0; kt < 16; kt++) {
        int k0 = kt * 8;
        unsigned ahi[2][4], alo[2][4];
        #pragma unroll
        for (int mt = 0; mt < 2; mt++) {
            int r0 = ar0 + mt * 16;
            int r1 = r0 + 8;
            float f0 = As[r0 * A_STRIDE + k0 + qid];
            float f1 = As[r1 * A_STRIDE + k0 + qid];
            float f2 = As[r0 * A_STRIDE + k0 + qid + 4];
            float f3 = As[r1 * A_STRIDE + k0 + qid + 4];
            float h0 = trunc13(f0), h1 = trunc13(f1), h2 = trunc13(f2), h3 = trunc13(f3);
            ahi[mt][0] = __float_as_uint(h0); alo[mt][0] = __float_as_uint(f0 - h0);
            ahi[mt][1] = __float_as_uint(h1); alo[mt][1] = __float_as_uint(f1 - h1);
            ahi[mt][2] = __float_as_uint(h2); alo[mt][2] = __float_as_uint(f2 - h2);
            ahi[mt][3] = __float_as_uint(h3); alo[mt][3] = __float_as_uint(f3 - h3);
        }
        #pragma unroll
        for (int nt = 0; nt < NT; nt++) {
            int c = col0 + nt * 8 + grp;
            float4 pb = PB[((kt * BN) + c) * 4 + qid];
            unsigned bh[2] = { __float_as_uint(pb.x), __float_as_uint(pb.z) };
            unsigned bl[2] = { __float_as_uint(pb.y), __float_as_uint(pb.w) };
            #pragma unroll
            for (int mt = 0; mt < 2; mt++) {
                mma_tf32(acc[mt][nt], ahi[mt], bh);
                mma_tf32(acc[mt][nt], ahi[mt], bl);
                mma_tf32(acc[mt][nt], alo[mt], bh);
            }
        }
    }
    #pragma unroll
    for (int mt = 0; mt < 2; mt++) {
        int r0 = m0 + warp_m * 32 + mt * 16 + grp;
        int r1 = r0 + 8;
        #pragma unroll
        for (int nt = 0; nt < NT; nt++) {
            int c = col0 + nt * 8 + qid * 2;
            if (r0 < M) {
                C[(size_t)r0 * BN + c]     = acc[mt][nt][0];
                C[(size_t)r0 * BN + c + 1] = acc[mt][nt][1];
            }
            if (r1 < M) {
                C[(size_t)r1 * BN + c]     = acc[mt][nt][2];
                C[(size_t)r1 * BN + c + 1] = acc[mt][nt][3];
            }
        }
    }
}

// ---------------------------------------------------------------------------
// 5) Aggregation D=128: warp per node, CSR gather (unroll 4), +self,+bias,ReLU
// ---------------------------------------------------------------------------
template <bool RELU>
__global__ void agg128_kernel(const float* __restrict__ hin,
                              float* __restrict__ hout,
                              const float* __restrict__ bias, int N) {
    int warp = (blockIdx.x * blockDim.x + threadIdx.x) >> 5;
    int lane = threadIdx.x & 31;
    if (warp >= N) return;

    float dn = g_dinv[warp];
    float acc[4];
    {
        float ws = dn * dn;
        float4 v = *(const float4*)(hin + (size_t)warp * 128 + lane * 4);
        acc[0] = ws * v.x; acc[1] = ws * v.y; acc[2] = ws * v.z; acc[3] = ws * v.w;
    }
    int e = g_rowptr[warp];
    const int e1 = g_rowptr[warp + 1];
    for (; e + 4 <= e1; e += 4) {
        int s0 = g_col[e], s1 = g_col[e + 1], s2 = g_col[e + 2], s3 = g_col[e + 3];
        float w0 = g_dinv[s0] * dn, w1 = g_dinv[s1] * dn;
        float w2 = g_dinv[s2] * dn, w3 = g_dinv[s3] * dn;
        float4 v0 = *(const float4*)(hin + (size_t)s0 * 128 + lane * 4);
        float4 v1 = *(const float4*)(hin + (size_t)s1 * 128 + lane * 4);
        float4 v2 = *(const float4*)(hin + (size_t)s2 * 128 + lane * 4);
        float4 v3 = *(const float4*)(hin + (size_t)s3 * 128 + lane * 4);
        acc[0] += w0 * v0.x + w1 * v1.x + w2 * v2.x + w3 * v3.x;
        acc[1] += w0 * v0.y + w1 * v1.y + w2 * v2.y + w3 * v3.y;
        acc[2] += w0 * v0.z + w1 * v1.z + w2 * v2.z + w3 * v3.z;
        acc[3] += w0 * v0.w + w1 * v1.w + w2 * v2.w + w3 * v3.w;
    }
    for (; e < e1; e++) {
        int s = g_col[e];
        float w = g_dinv[s] * dn;
        float4 v = *(const float4*)(hin + (size_t)s * 128 + lane * 4);
        acc[0] += w * v.x; acc[1] += w * v.y; acc[2] += w * v.z; acc[3] += w * v.w;
    }
    float4 b = *(const float4*)(bias + lane * 4);
    float4 o = make_float4(acc[0] + b.x, acc[1] + b.y, acc[2] + b.z, acc[3] + b.w);
    if (RELU) {
        o.x = fmaxf(o.x, 0.f); o.y = fmaxf(o.y, 0.f);
        o.z = fmaxf(o.z, 0.f); o.w = fmaxf(o.w, 0.f);
    }
    *(float4*)(hout + (size_t)warp * 128 + lane * 4) = o;
}

// ---------------------------------------------------------------------------
// 5b) Aggregation D=64 with fused output head (unroll 4)
// ---------------------------------------------------------------------------
__global__ void agg64_out_kernel(const float* __restrict__ hin,
                                 float* __restrict__ hout,
                                 const float* __restrict__ bias,
                                 const float* __restrict__ Wout,
                                 const float* __restrict__ bout,
                                 float* __restrict__ out, int N) {
    int warp = (blockIdx.x * blockDim.x + threadIdx.x) >> 5;
    int lane = threadIdx.x & 31;
    if (warp >= N) return;

    float dn = g_dinv[warp];
    float a0, a1;
    {
        float ws = dn * dn;
        float2 v = *(const float2*)(hin + (size_t)warp * 64 + lane * 2);
        a0 = ws * v.x; a1 = ws * v.y;
    }
    int e = g_rowptr[warp];
    const int e1 = g_rowptr[warp + 1];
    for (; e + 4 <= e1; e += 4) {
        int s0 = g_col[e], s1 = g_col[e + 1], s2 = g_col[e + 2], s3 = g_col[e + 3];
        float w0 = g_dinv[s0] * dn, w1 = g_dinv[s1] * dn;
        float w2 = g_dinv[s2] * dn, w3 = g_dinv[s3] * dn;
        float2 v0 = *(const float2*)(hin + (size_t)s0 * 64 + lane * 2);
        float2 v1 = *(const float2*)(hin + (size_t)s1 * 64 + lane * 2);
        float2 v2 = *(const float2*)(hin + (size_t)s2 * 64 + lane * 2);
        float2 v3 = *(const float2*)(hin + (size_t)s3 * 64 + lane * 2);
        a0 += w0 * v0.x + w1 * v1.x + w2 * v2.x + w3 * v3.x;
        a1 += w0 * v0.y + w1 * v1.y + w2 * v2.y + w3 * v3.y;
    }
    for (; e < e1; e++) {
        int s = g_col[e];
        float w = g_dinv[s] * dn;
        float2 v = *(const float2*)(hin + (size_t)s * 64 + lane * 2);
        a0 += w * v.x; a1 += w * v.y;
    }
    float2 b = *(const float2*)(bias + lane * 2);
    float2 o = make_float2(a0 + b.x, a1 + b.y);
    *(float2*)(hout + (size_t)warp * 64 + lane * 2) = o;

    int c0 = lane * 2;
    float p0 = o.x * __ldg(&Wout[c0 * 2])     + o.y * __ldg(&Wout[(c0 + 1) * 2]);
    float p1 = o.x * __ldg(&Wout[c0 * 2 + 1]) + o.y * __ldg(&Wout[(c0 + 1) * 2 + 1]);
    #pragma unroll
    for (int off = 16; off > 0; off >>= 1) {
        p0 += __shfl_xor_sync(0xffffffffu, p0, off);
        p1 += __shfl_xor_sync(0xffffffffu, p1, off);
    }
    if (lane == 0) {
        out[(size_t)warp * 2 + 0] = p0 + __ldg(&bout[0]);
        out[(size_t)warp * 2 + 1] = p1 + __ldg(&bout[1]);
    }
}

// ---------------------------------------------------------------------------
extern "C" void kernel_launch(void* const* d_in, const int* in_sizes, int n_in,
                              void* d_out, int out_size) {
    (void)n_in; (void)out_size;
    const float* x    = (const float*)d_in[0];
    const int*   ei   = (const int*)d_in[1];   // int32 (JAX default x64 off)
    const float* W1   = (const float*)d_in[2];
    const float* b1   = (const float*)d_in[3];
    const float* W2   = (const float*)d_in[4];
    const float* b2   = (const float*)d_in[5];
    const float* W3   = (const float*)d_in[6];
    const float* b3   = (const float*)d_in[7];
    const float* Wout = (const float*)d_in[8];
    const float* bout = (const float*)d_in[9];

    int N = in_sizes[0] / 128;
    int E = in_sizes[1] / 2;

    float* out  = (float*)d_out;
    float* hout = out + (size_t)N * 2;   // tuple layout: out[N,2] then h[N,64]

    float* buf0; cudaGetSymbolAddress((void**)&buf0, g_buf0);
    float* buf1; cudaGetSymbolAddress((void**)&buf1, g_buf1);
    float4* pb1; cudaGetSymbolAddress((void**)&pb1, g_pb1);
    float4* pb2; cudaGetSymbolAddress((void**)&pb2, g_pb2);
    float4* pb3; cudaGetSymbolAddress((void**)&pb3, g_pb3);

    const int* src = ei;
    const int* dst = ei + E;

    // dynamic smem opt-in for the staged-A GEMMs (host API, capture-safe)
    static bool attr_done = false;
    if (!attr_done) {
        cudaFuncSetAttribute(mma_gemm_kernel<128>,
                             cudaFuncAttributeMaxDynamicSharedMemorySize, A_SMEM_BYTES);
        cudaFuncSetAttribute(mma_gemm_kernel<64>,
                             cudaFuncAttributeMaxDynamicSharedMemorySize, A_SMEM_BYTES);
        attr_done = true;
    }

    // weight pre-split (fragment order)
    pack_w_kernel<<<(16 * 128 * 4 + 255) / 256, 256>>>(W1, pb1, 128);
    pack_w_kernel<<<(16 * 128 * 4 + 255) / 256, 256>>>(W2, pb2, 128);
    pack_w_kernel<<<(16 * 64 * 4 + 255) / 256, 256>>>(W3, pb3, 64);

    // CSR build
    int nb = (N + 1023) / 1024;
    int e4 = (E + 3) / 4;
    zero_deg_kernel<<<(N + 255) / 256, 256>>>(N);
    deg_kernel<<<(e4 + 255) / 256, 256>>>(dst, E, N);
    scan1_kernel<<<nb, 256>>>(N);
    scan2_kernel<<<1, 32>>>(nb, N);
    scan3_kernel<<<nb, 256>>>(N);
    fill_kernel<<<(e4 + 255) / 256, 256>>>(src, dst, E, N);

    int gM = (N + 127) / 128;
    int gW = (N * 32 + 255) / 256;

    // Layer 1
    mma_gemm_kernel<128><<<gM, 256, A_SMEM_BYTES>>>(x, pb1, buf0, N);
    agg128_kernel<true><<<gW, 256>>>(buf0, buf1, b1, N);
    // Layer 2
    mma_gemm_kernel<128><<<gM, 256, A_SMEM_BYTES>>>(buf1, pb2, buf0, N);
    agg128_kernel<true><<<gW, 256>>>(buf0, buf1, b2, N);
    // Layer 3 + fused output head
    mma_gemm_kernel<64><<<gM, 256, A_SMEM_BYTES>>>(buf1, pb3, buf0, N);
    agg64_out_kernel<<<gW, 256>>>(buf0, hout, b3, Wout, bout, out, N);
}

// round 12
// speedup vs baseline: 1.2905x; 1.1020x over previous
#include <cuda_runtime.h>
#include <cstdint>

#define NMAX 40000
#define EMAX 640000

// Scratch (device globals: allocation-free per harness rules)
__device__ int   g_deg[NMAX];
__device__ int   g_rowptr[NMAX + 1];
__device__ int   g_cursor[NMAX];
__device__ int   g_col[EMAX];
__device__ float g_dinv[NMAX];
__device__ int   g_bsum[64];
__device__ float g_buf0[(size_t)NMAX * 128];
__device__ float g_buf1[(size_t)NMAX * 128];
// Pre-split tf32 fragment-ordered weights: ((kt*BN)+c)*4+qid -> {hi,lo,hi,lo}
__device__ float4 g_pb1[16 * 128 * 4];
__device__ float4 g_pb2[16 * 128 * 4];
__device__ float4 g_pb3[16 * 64 * 4];

// ---------------------------------------------------------------------------
__device__ __forceinline__ float trunc13(float f) {
    return __uint_as_float(__float_as_uint(f) & 0xffffe000u);
}

// ---------------------------------------------------------------------------
// 0) zero degree array
// ---------------------------------------------------------------------------
__global__ void zero_deg_kernel(int N) {
    int i = blockIdx.x * blockDim.x + threadIdx.x;
    if (i < N) g_deg[i] = 0;
}

// ---------------------------------------------------------------------------
// 1) degree count (edges by dst), 4 edges per thread via int4
// ---------------------------------------------------------------------------
__global__ void deg_kernel(const int* __restrict__ dst, int E, int N) {
    int i = blockIdx.x * blockDim.x + threadIdx.x;
    int e0 = i * 4;
    if (e0 + 4 <= E) {
        int4 d4 = *(const int4*)(dst + e0);
        atomicAdd(&g_deg[max(0, min(d4.x, N - 1))], 1);
        atomicAdd(&g_deg[max(0, min(d4.y, N - 1))], 1);
        atomicAdd(&g_deg[max(0, min(d4.z, N - 1))], 1);
        atomicAdd(&g_deg[max(0, min(d4.w, N - 1))], 1);
    } else {
        for (int e = e0; e < E; e++)
            atomicAdd(&g_deg[max(0, min(dst[e], N - 1))], 1);
    }
}

// ---------------------------------------------------------------------------
// 2) hierarchical exclusive scan -> rowptr/cursor + dinv
// ---------------------------------------------------------------------------
__global__ void scan1_kernel(int N) {
    __shared__ int sh[256];
    int t = threadIdx.x;
    int base = blockIdx.x * 1024 + t * 4;
    int s = 0;
    #pragma unroll
    for (int i = 0; i < 4; i++) if (base + i < N) s += g_deg[base + i];
    sh[t] = s;
    __syncthreads();
    #pragma unroll
    for (int off = 128; off > 0; off >>= 1) {
        if (t < off) sh[t] += sh[t + off];
        __syncthreads();
    }
    if (t == 0) g_bsum[blockIdx.x] = sh[0];
}

__global__ void scan2_kernel(int nb, int N) {
    if (threadIdx.x == 0) {
        int run = 0;
        for (int i = 0; i < nb; i++) { int v = g_bsum[i]; g_bsum[i] = run; run += v; }
        g_rowptr[N] = run;
    }
}

__global__ void scan3_kernel(int N) {
    __shared__ int sh[256];
    int t = threadIdx.x;
    int base = blockIdx.x * 1024 + t * 4;
    int v[4];
    int s = 0;
    #pragma unroll
    for (int i = 0; i < 4; i++) {
        v[i] = (base + i < N) ? g_deg[base + i] : 0;
        s += v[i];
    }
    sh[t] = s;
    __syncthreads();
    #pragma unroll
    for (int off = 1; off < 256; off <<= 1) {
        int x = (t >= off) ? sh[t - off] : 0;
        __syncthreads();
        sh[t] += x;
        __syncthreads();
    }
    int run = g_bsum[blockIdx.x] + sh[t] - s;
    #pragma unroll
    for (int i = 0; i < 4; i++) {
        int idx = base + i;
        if (idx < N) {
            g_rowptr[idx] = run;
            g_cursor[idx] = run;
            g_dinv[idx]   = rsqrtf((float)v[i] + 1.0f);
            run += v[i];
        }
    }
}

// ---------------------------------------------------------------------------
// 3) CSR fill, 4 edges per thread via int4
// ---------------------------------------------------------------------------
__global__ void fill_kernel(const int* __restrict__ src,
                            const int* __restrict__ dst, int E, int N) {
    int i = blockIdx.x * blockDim.x + threadIdx.x;
    int e0 = i * 4;
    if (e0 + 4 <= E) {
        int4 d4 = *(const int4*)(dst + e0);
        int4 s4 = *(const int4*)(src + e0);
        int p0 = atomicAdd(&g_cursor[max(0, min(d4.x, N - 1))], 1);
        int p1 = atomicAdd(&g_cursor[max(0, min(d4.y, N - 1))], 1);
        int p2 = atomicAdd(&g_cursor[max(0, min(d4.z, N - 1))], 1);
        int p3 = atomicAdd(&g_cursor[max(0, min(d4.w, N - 1))], 1);
        g_col[p0] = max(0, min(s4.x, N - 1));
        g_col[p1] = max(0, min(s4.y, N - 1));
        g_col[p2] = max(0, min(s4.z, N - 1));
        g_col[p3] = max(0, min(s4.w, N - 1));
    } else {
        for (int e = e0; e < E; e++) {
            int pos = atomicAdd(&g_cursor[max(0, min(dst[e], N - 1))], 1);
            g_col[pos] = max(0, min(src[e], N - 1));
        }
    }
}

// ---------------------------------------------------------------------------
// 3b) pack weights into fragment-ordered split form (once per launch, cheap)
// ---------------------------------------------------------------------------
__global__ void pack_w_kernel(const float* __restrict__ W, float4* __restrict__ PB, int BN) {
    int i = blockIdx.x * blockDim.x + threadIdx.x;
    int total = 16 * BN * 4;
    if (i >= total) return;
    int qid = i & 3;
    int c   = (i >> 2) % BN;
    int kt  = (i >> 2) / BN;
    float f0 = W[(kt * 8 + qid) * BN + c];
    float f1 = W[(kt * 8 + qid + 4) * BN + c];
    float4 v;
    v.x = trunc13(f0); v.y = f0 - v.x;
    v.z = trunc13(f1); v.w = f1 - v.z;
    PB[i] = v;
}

// ---------------------------------------------------------------------------
// 4) Tensor-core GEMM, 3xTF32, A staged through shared memory (conflict-free),
//    pre-split B fragments from global (L2-resident)
// ---------------------------------------------------------------------------
__device__ __forceinline__ void mma_tf32(float* c, const unsigned* a, const unsigned* b) {
    asm volatile(
        "mma.sync.aligned.m16n8k8.row.col.f32.tf32.tf32.f32 "
        "{%0,%1,%2,%3}, {%4,%5,%6,%7}, {%8,%9}, {%0,%1,%2,%3};\n"
        : "+f"(c[0]), "+f"(c[1]), "+f"(c[2]), "+f"(c[3])
        : "r"(a[0]), "r"(a[1]), "r"(a[2]), "r"(a[3]), "r"(b[0]), "r"(b[1]));
}

#define A_STRIDE 132   // floats per row (128 + 4 pad -> conflict-free LDS)
#define A_SMEM_BYTES (128 * A_STRIDE * 4)

template <int BN>
__global__ void __launch_bounds__(256, 1)
mma_gemm_kernel(const float* __restrict__ A,
                const float4* __restrict__ PB,
                float* __restrict__ C, int M) {
    constexpr int NT = BN / 16;
    extern __shared__ float As[];   // [128][A_STRIDE]
    int tid = threadIdx.x;
    int wid = tid >> 5, lane = tid & 31;
    int warp_m = wid >> 1, warp_n = wid & 1;
    int grp = lane >> 2, qid = lane & 3;
    int m0 = blockIdx.x * 128;
    int col0 = warp_n * (BN / 2);

    // ---- stage A tile: coalesced float4 loads ----
    for (int idx = tid; idx < 128 * 32; idx += 256) {
        int r = idx >> 5;
        int c4 = (idx & 31) * 4;
        int gr = min(m0 + r, M - 1);
        float4 v = *(const float4*)(A + (size_t)gr * 128 + c4);
        *(float4*)(As + r * A_STRIDE + c4) = v;
    }
    __syncthreads();

    float acc[2][NT][4];
    #pragma unroll
    for (int mt = 0; mt < 2; mt++)
        #pragma unroll
        for (int nt = 0; nt < NT; nt++)
            #pragma unroll
            for (int j = 0; j < 4; j++) acc[mt][nt][j] = 0.f;

    int ar0 = warp_m * 32 + grp;       // local row for mt=0
    #pragma unroll 2
    for (int kt = 0; kt < 16; kt++) {
        int k0 = kt * 8;
        unsigned ahi[2][4], alo[2][4];
        #pragma unroll
        for (int mt = 0; mt < 2; mt++) {
            int r0 = ar0 + mt * 16;
            int r1 = r0 + 8;
            float f0 = As[r0 * A_STRIDE + k0 + qid];
            float f1 = As[r1 * A_STRIDE + k0 + qid];
            float f2 = As[r0 * A_STRIDE + k0 + qid + 4];
            float f3 = As[r1 * A_STRIDE + k0 + qid + 4];
            float h0 = trunc13(f0), h1 = trunc13(f1), h2 = trunc13(f2), h3 = trunc13(f3);
            ahi[mt][0] = __float_as_uint(h0); alo[mt][0] = __float_as_uint(f0 - h0);
            ahi[mt][1] = __float_as_uint(h1); alo[mt][1] = __float_as_uint(f1 - h1);
            ahi[mt][2] = __float_as_uint(h2); alo[mt][2] = __float_as_uint(f2 - h2);
            ahi[mt][3] = __float_as_uint(h3); alo[mt][3] = __float_as_uint(f3 - h3);
        }
        #pragma unroll
        for (int nt = 0; nt < NT; nt++) {
            int c = col0 + nt * 8 + grp;
            float4 pb = PB[((kt * BN) + c) * 4 + qid];
            unsigned bh[2] = { __float_as_uint(pb.x), __float_as_uint(pb.z) };
            unsigned bl[2] = { __float_as_uint(pb.y), __float_as_uint(pb.w) };
            #pragma unroll
            for (int mt = 0; mt < 2; mt++) {
                mma_tf32(acc[mt][nt], ahi[mt], bh);
                mma_tf32(acc[mt][nt], ahi[mt], bl);
                mma_tf32(acc[mt][nt], alo[mt], bh);
            }
        }
    }
    #pragma unroll
    for (int mt = 0; mt < 2; mt++) {
        int r0 = m0 + warp_m * 32 + mt * 16 + grp;
        int r1 = r0 + 8;
        #pragma unroll
        for (int nt = 0; nt < NT; nt++) {
            int c = col0 + nt * 8 + qid * 2;
            if (r0 < M) {
                C[(size_t)r0 * BN + c]     = acc[mt][nt][0];
                C[(size_t)r0 * BN + c + 1] = acc[mt][nt][1];
            }
            if (r1 < M) {
                C[(size_t)r1 * BN + c]     = acc[mt][nt][2];
                C[(size_t)r1 * BN + c + 1] = acc[mt][nt][3];
            }
        }
    }
}

// ---------------------------------------------------------------------------
// 5) Aggregation D=128: warp per node, CSR gather (unroll 4), +self,+bias,ReLU
// ---------------------------------------------------------------------------
template <bool RELU>
__global__ void agg128_kernel(const float* __restrict__ hin,
                              float* __restrict__ hout,
                              const float* __restrict__ bias, int N) {
    int warp = (blockIdx.x * blockDim.x + threadIdx.x) >> 5;
    int lane = threadIdx.x & 31;
    if (warp >= N) return;

    float dn = g_dinv[warp];
    float acc[4];
    {
        float ws = dn * dn;
        float4 v = *(const float4*)(hin + (size_t)warp * 128 + lane * 4);
        acc[0] = ws * v.x; acc[1] = ws * v.y; acc[2] = ws * v.z; acc[3] = ws * v.w;
    }
    int e = g_rowptr[warp];
    const int e1 = g_rowptr[warp + 1];
    for (; e + 4 <= e1; e += 4) {
        int s0 = g_col[e], s1 = g_col[e + 1], s2 = g_col[e + 2], s3 = g_col[e + 3];
        float w0 = g_dinv[s0] * dn, w1 = g_dinv[s1] * dn;
        float w2 = g_dinv[s2] * dn, w3 = g_dinv[s3] * dn;
        float4 v0 = *(const float4*)(hin + (size_t)s0 * 128 + lane * 4);
        float4 v1 = *(const float4*)(hin + (size_t)s1 * 128 + lane * 4);
        float4 v2 = *(const float4*)(hin + (size_t)s2 * 128 + lane * 4);
        float4 v3 = *(const float4*)(hin + (size_t)s3 * 128 + lane * 4);
        acc[0] += w0 * v0.x + w1 * v1.x + w2 * v2.x + w3 * v3.x;
        acc[1] += w0 * v0.y + w1 * v1.y + w2 * v2.y + w3 * v3.y;
        acc[2] += w0 * v0.z + w1 * v1.z + w2 * v2.z + w3 * v3.z;
        acc[3] += w0 * v0.w + w1 * v1.w + w2 * v2.w + w3 * v3.w;
    }
    for (; e < e1; e++) {
        int s = g_col[e];
        float w = g_dinv[s] * dn;
        float4 v = *(const float4*)(hin + (size_t)s * 128 + lane * 4);
        acc[0] += w * v.x; acc[1] += w * v.y; acc[2] += w * v.z; acc[3] += w * v.w;
    }
    float4 b = *(const float4*)(bias + lane * 4);
    float4 o = make_float4(acc[0] + b.x, acc[1] + b.y, acc[2] + b.z, acc[3] + b.w);
    if (RELU) {
        o.x = fmaxf(o.x, 0.f); o.y = fmaxf(o.y, 0.f);
        o.z = fmaxf(o.z, 0.f); o.w = fmaxf(o.w, 0.f);
    }
    *(float4*)(hout + (size_t)warp * 128 + lane * 4) = o;
}

// ---------------------------------------------------------------------------
// 5b) Aggregation D=64 with fused output head (unroll 4)
// ---------------------------------------------------------------------------
__global__ void agg64_out_kernel(const float* __restrict__ hin,
                                 float* __restrict__ hout,
                                 const float* __restrict__ bias,
                                 const float* __restrict__ Wout,
                                 const float* __restrict__ bout,
                                 float* __restrict__ out, int N) {
    int warp = (blockIdx.x * blockDim.x + threadIdx.x) >> 5;
    int lane = threadIdx.x & 31;
    if (warp >= N) return;

    float dn = g_dinv[warp];
    float a0, a1;
    {
        float ws = dn * dn;
        float2 v = *(const float2*)(hin + (size_t)warp * 64 + lane * 2);
        a0 = ws * v.x; a1 = ws * v.y;
    }
    int e = g_rowptr[warp];
    const int e1 = g_rowptr[warp + 1];
    for (; e + 4 <= e1; e += 4) {
        int s0 = g_col[e], s1 = g_col[e + 1], s2 = g_col[e + 2], s3 = g_col[e + 3];
        float w0 = g_dinv[s0] * dn, w1 = g_dinv[s1] * dn;
        float w2 = g_dinv[s2] * dn, w3 = g_dinv[s3] * dn;
        float2 v0 = *(const float2*)(hin + (size_t)s0 * 64 + lane * 2);
        float2 v1 = *(const float2*)(hin + (size_t)s1 * 64 + lane * 2);
        float2 v2 = *(const float2*)(hin + (size_t)s2 * 64 + lane * 2);
        float2 v3 = *(const float2*)(hin + (size_t)s3 * 64 + lane * 2);
        a0 += w0 * v0.x + w1 * v1.x + w2 * v2.x + w3 * v3.x;
        a1 += w0 * v0.y + w1 * v1.y + w2 * v2.y + w3 * v3.y;
    }
    for (; e < e1; e++) {
        int s = g_col[e];
        float w = g_dinv[s] * dn;
        float2 v = *(const float2*)(hin + (size_t)s * 64 + lane * 2);
        a0 += w * v.x; a1 += w * v.y;
    }
    float2 b = *(const float2*)(bias + lane * 2);
    float2 o = make_float2(a0 + b.x, a1 + b.y);
    *(float2*)(hout + (size_t)warp * 64 + lane * 2) = o;

    int c0 = lane * 2;
    float p0 = o.x * __ldg(&Wout[c0 * 2])     + o.y * __ldg(&Wout[(c0 + 1) * 2]);
    float p1 = o.x * __ldg(&Wout[c0 * 2 + 1]) + o.y * __ldg(&Wout[(c0 + 1) * 2 + 1]);
    #pragma unroll
    for (int off = 16; off > 0; off >>= 1) {
        p0 += __shfl_xor_sync(0xffffffffu, p0, off);
        p1 += __shfl_xor_sync(0xffffffffu, p1, off);
    }
    if (lane == 0) {
        out[(size_t)warp * 2 + 0] = p0 + __ldg(&bout[0]);
        out[(size_t)warp * 2 + 1] = p1 + __ldg(&bout[1]);
    }
}

// ---------------------------------------------------------------------------
extern "C" void kernel_launch(void* const* d_in, const int* in_sizes, int n_in,
                              void* d_out, int out_size) {
    (void)n_in; (void)out_size;
    const float* x    = (const float*)d_in[0];
    const int*   ei   = (const int*)d_in[1];   // int32 (JAX default x64 off)
    const float* W1   = (const float*)d_in[2];
    const float* b1   = (const float*)d_in[3];
    const float* W2   = (const float*)d_in[4];
    const float* b2   = (const float*)d_in[5];
    const float* W3   = (const float*)d_in[6];
    const float* b3   = (const float*)d_in[7];
    const float* Wout = (const float*)d_in[8];
    const float* bout = (const float*)d_in[9];

    int N = in_sizes[0] / 128;
    int E = in_sizes[1] / 2;

    float* out  = (float*)d_out;
    float* hout = out + (size_t)N * 2;   // tuple layout: out[N,2] then h[N,64]

    float* buf0; cudaGetSymbolAddress((void**)&buf0, g_buf0);
    float* buf1; cudaGetSymbolAddress((void**)&buf1, g_buf1);
    float4* pb1; cudaGetSymbolAddress((void**)&pb1, g_pb1);
    float4* pb2; cudaGetSymbolAddress((void**)&pb2, g_pb2);
    float4* pb3; cudaGetSymbolAddress((void**)&pb3, g_pb3);

    const int* src = ei;
    const int* dst = ei + E;

    // one-time host-side setup (attrs, side stream, fork/join events)
    static cudaStream_t s2 = nullptr;
    static cudaEvent_t ev_fork = nullptr, ev_join = nullptr;
    if (!s2) {
        cudaFuncSetAttribute(mma_gemm_kernel<128>,
                             cudaFuncAttributeMaxDynamicSharedMemorySize, A_SMEM_BYTES);
        cudaFuncSetAttribute(mma_gemm_kernel<64>,
                             cudaFuncAttributeMaxDynamicSharedMemorySize, A_SMEM_BYTES);
        cudaStreamCreateWithFlags(&s2, cudaStreamNonBlocking);
        cudaEventCreateWithFlags(&ev_fork, cudaEventDisableTiming);
        cudaEventCreateWithFlags(&ev_join, cudaEventDisableTiming);
    }

    int nb = (N + 1023) / 1024;
    int e4 = (E + 3) / 4;
    int gM = (N + 127) / 128;
    int gW = (N * 32 + 255) / 256;

    // ---- fork: side stream runs weight packing + GEMM1 (independent of CSR) ----
    cudaEventRecord(ev_fork, 0);
    cudaStreamWaitEvent(s2, ev_fork, 0);

    // branch B (s2): pack1 -> gemm1 -> pack2 -> pack3
    pack_w_kernel<<<(16 * 128 * 4 + 255) / 256, 256, 0, s2>>>(W1, pb1, 128);
    mma_gemm_kernel<128><<<gM, 256, A_SMEM_BYTES, s2>>>(x, pb1, buf0, N);
    pack_w_kernel<<<(16 * 128 * 4 + 255) / 256, 256, 0, s2>>>(W2, pb2, 128);
    pack_w_kernel<<<(16 * 64 * 4 + 255) / 256, 256, 0, s2>>>(W3, pb3, 64);
    cudaEventRecord(ev_join, s2);

    // branch A (capture stream): CSR build
    zero_deg_kernel<<<(N + 255) / 256, 256>>>(N);
    deg_kernel<<<(e4 + 255) / 256, 256>>>(dst, E, N);
    scan1_kernel<<<nb, 256>>>(N);
    scan2_kernel<<<1, 32>>>(nb, N);
    scan3_kernel<<<nb, 256>>>(N);
    fill_kernel<<<(e4 + 255) / 256, 256>>>(src, dst, E, N);

    // ---- join: agg1 needs CSR (branch A) + gemm1 output (branch B) ----
    cudaStreamWaitEvent(0, ev_join, 0);

    agg128_kernel<true><<<gW, 256>>>(buf0, buf1, b1, N);
    // Layer 2
    mma_gemm_kernel<128><<<gM, 256, A_SMEM_BYTES>>>(buf1, pb2, buf0, N);
    agg128_kernel<true><<<gW, 256>>>(buf0, buf1, b2, N);
    // Layer 3 + fused output head
    mma_gemm_kernel<64><<<gM, 256, A_SMEM_BYTES>>>(buf1, pb3, buf0, N);
    agg64_out_kernel<<<gW, 256>>>(buf0, hout, b3, Wout, bout, out, N);
}